// round 3
// baseline (speedup 1.0000x reference)
#include <cuda_runtime.h>
#include <math.h>

// Problem constants
#define B_  8
#define S_  128
#define N_  64
#define DK_ 256
#define H_  8
#define DH_ 32

static const int M_TOK = B_ * S_ * N_;  // 65536 "token" rows for the dense GEMMs

// Scratch (device globals — no allocation allowed in kernel_launch)
__device__ float g_Qp[(size_t)B_ * S_ * N_ * DK_];
__device__ float g_Kp[(size_t)B_ * S_ * N_ * DK_];
__device__ float g_Vp[(size_t)B_ * S_ * N_ * DK_];
__device__ float g_At[(size_t)B_ * S_ * N_ * DK_];

// ---------------------------------------------------------------------------
// GEMM: C[M,256] = A[M,256] @ W[256,256] + bias[256]
// Block tile 64x64, BK=32, 256 threads, 4x4 microtile.
// ---------------------------------------------------------------------------
__global__ __launch_bounds__(256) void gemm_bias_kernel(
    const float* __restrict__ A, const float* __restrict__ W,
    const float* __restrict__ bias, float* __restrict__ C)
{
    __shared__ float As[32][68];   // transposed A tile [k][m], padded
    __shared__ float Ws[32][64];   // W tile [k][n]

    const int tid = threadIdx.x;
    const int tx = tid & 15;       // col group (4 cols each)
    const int ty = tid >> 4;       // row group (4 rows each)
    const int rowBase = blockIdx.x * 64;
    const int colBase = blockIdx.y * 64;

    float acc[4][4] = {};

    for (int kk = 0; kk < 256; kk += 32) {
        // Load A tile: 64 rows x 32 k  = 512 float4
        #pragma unroll
        for (int i = 0; i < 2; i++) {
            int id = tid + i * 256;
            int r = id >> 3;        // 0..63
            int vv = id & 7;        // 0..7 (float4 along k)
            float4 a = *reinterpret_cast<const float4*>(
                &A[(size_t)(rowBase + r) * 256 + kk + vv * 4]);
            As[vv * 4 + 0][r] = a.x;
            As[vv * 4 + 1][r] = a.y;
            As[vv * 4 + 2][r] = a.z;
            As[vv * 4 + 3][r] = a.w;
        }
        // Load W tile: 32 k-rows x 64 n = 512 float4
        #pragma unroll
        for (int i = 0; i < 2; i++) {
            int id = tid + i * 256;
            int r = id >> 4;        // k row 0..31
            int vv = id & 15;       // 0..15 (float4 along n)
            float4 w = *reinterpret_cast<const float4*>(
                &W[(size_t)(kk + r) * 256 + colBase + vv * 4]);
            *reinterpret_cast<float4*>(&Ws[r][vv * 4]) = w;
        }
        __syncthreads();

        #pragma unroll
        for (int k = 0; k < 32; k++) {
            float4 av = *reinterpret_cast<const float4*>(&As[k][ty * 4]);
            float4 wv = *reinterpret_cast<const float4*>(&Ws[k][tx * 4]);
            float a[4] = {av.x, av.y, av.z, av.w};
            float w[4] = {wv.x, wv.y, wv.z, wv.w};
            #pragma unroll
            for (int i = 0; i < 4; i++)
                #pragma unroll
                for (int j = 0; j < 4; j++)
                    acc[i][j] += a[i] * w[j];
        }
        __syncthreads();
    }

    // Epilogue: add bias, vector store
    float4 bv = *reinterpret_cast<const float4*>(&bias[colBase + tx * 4]);
    #pragma unroll
    for (int i = 0; i < 4; i++) {
        float4 o;
        o.x = acc[i][0] + bv.x;
        o.y = acc[i][1] + bv.y;
        o.z = acc[i][2] + bv.z;
        o.w = acc[i][3] + bv.w;
        *reinterpret_cast<float4*>(
            &C[(size_t)(rowBase + ty * 4 + i) * 256 + colBase + tx * 4]) = o;
    }
}

// ---------------------------------------------------------------------------
// Attention: one block per (b, s, h). N=64 agents, DH=32.
// scores = Qh @ Kh^T / sqrt(32); softmax over m; attn = P @ Vh.
// Writes normalized weights to w_out and attn (head-gathered) to g_At.
// ---------------------------------------------------------------------------
__global__ __launch_bounds__(256) void attn_kernel(float* __restrict__ w_out)
{
    __shared__ float Qs[64][33];
    __shared__ float Ks[64][33];
    __shared__ float Vs[64][33];
    __shared__ float P[64][65];
    __shared__ float rinv[64];

    const int blk = blockIdx.x;            // ((b*S + s) * H + h)
    const int h = blk % H_;
    const int bs = blk / H_;
    const int s = bs % S_;
    const int b = bs / S_;

    const size_t base = ((size_t)(b * S_ + s) * N_) * DK_ + (size_t)h * DH_;
    const int tid = threadIdx.x;

    // Load Q/K/V head tiles: each 64 rows x 32 dims = 512 float4
    for (int i = tid; i < 512; i += 256) {
        int n = i >> 3;
        int vv = i & 7;
        size_t g = base + (size_t)n * DK_ + vv * 4;
        float4 q = *reinterpret_cast<const float4*>(&g_Qp[g]);
        Qs[n][vv * 4 + 0] = q.x; Qs[n][vv * 4 + 1] = q.y;
        Qs[n][vv * 4 + 2] = q.z; Qs[n][vv * 4 + 3] = q.w;
        float4 k = *reinterpret_cast<const float4*>(&g_Kp[g]);
        Ks[n][vv * 4 + 0] = k.x; Ks[n][vv * 4 + 1] = k.y;
        Ks[n][vv * 4 + 2] = k.z; Ks[n][vv * 4 + 3] = k.w;
        float4 v = *reinterpret_cast<const float4*>(&g_Vp[g]);
        Vs[n][vv * 4 + 0] = v.x; Vs[n][vv * 4 + 1] = v.y;
        Vs[n][vv * 4 + 2] = v.z; Vs[n][vv * 4 + 3] = v.w;
    }
    __syncthreads();

    // Scores
    const float scale = 0.17677669529663687f;  // 1/sqrt(32)
    for (int idx = tid; idx < 4096; idx += 256) {
        int n = idx >> 6;
        int m = idx & 63;
        float acc = 0.0f;
        #pragma unroll
        for (int d = 0; d < 32; d++) acc += Qs[n][d] * Ks[m][d];
        P[n][m] = acc * scale;
    }
    __syncthreads();

    // Row softmax (64 rows, one thread each)
    if (tid < 64) {
        float mx = -INFINITY;
        #pragma unroll 8
        for (int m = 0; m < 64; m++) mx = fmaxf(mx, P[tid][m]);
        float sum = 0.0f;
        #pragma unroll 8
        for (int m = 0; m < 64; m++) {
            float e = expf(P[tid][m] - mx);
            P[tid][m] = e;
            sum += e;
        }
        rinv[tid] = 1.0f / sum;
    }
    __syncthreads();

    // Normalize in place + write weights output
    const size_t wbase = ((size_t)((b * H_ + h) * S_ + s)) * (size_t)(N_ * N_);
    for (int idx = tid; idx < 4096; idx += 256) {
        int n = idx >> 6;
        float v = P[n][idx & 63] * rinv[n];
        P[n][idx & 63] = v;
        w_out[wbase + idx] = v;
    }
    __syncthreads();

    // attn = P @ Vh  -> write head-gathered into g_At (B,S,N,DK layout)
    for (int idx = tid; idx < 2048; idx += 256) {
        int n = idx >> 5;
        int d = idx & 31;
        float acc = 0.0f;
        #pragma unroll
        for (int m = 0; m < 64; m++) acc += P[n][m] * Vs[m][d];
        g_At[base + (size_t)n * DK_ + d] = acc;
    }
}

// ---------------------------------------------------------------------------
extern "C" void kernel_launch(void* const* d_in, const int* in_sizes, int n_in,
                              void* d_out, int out_size)
{
    const float* q   = (const float*)d_in[0];
    const float* k   = (const float*)d_in[1];
    const float* v   = (const float*)d_in[2];
    const float* WQw = (const float*)d_in[3];
    const float* WQb = (const float*)d_in[4];
    const float* WKw = (const float*)d_in[5];
    const float* WKb = (const float*)d_in[6];
    const float* WVw = (const float*)d_in[7];
    const float* WVb = (const float*)d_in[8];
    const float* WOw = (const float*)d_in[9];
    const float* WOb = (const float*)d_in[10];

    float* out = (float*)d_out;                              // (B,S,N,DK)
    float* wts = out + (size_t)M_TOK * DK_;                  // (B,H,S,N,N)

    float *Qp, *Kp, *Vp, *At;
    cudaGetSymbolAddress((void**)&Qp, g_Qp);
    cudaGetSymbolAddress((void**)&Kp, g_Kp);
    cudaGetSymbolAddress((void**)&Vp, g_Vp);
    cudaGetSymbolAddress((void**)&At, g_At);

    dim3 gg(M_TOK / 64, 256 / 64);   // (1024, 4)
    dim3 bb(256);

    gemm_bias_kernel<<<gg, bb>>>(q, WQw, WQb, Qp);
    gemm_bias_kernel<<<gg, bb>>>(k, WKw, WKb, Kp);
    gemm_bias_kernel<<<gg, bb>>>(v, WVw, WVb, Vp);

    attn_kernel<<<B_ * S_ * H_, 256>>>(wts);

    gemm_bias_kernel<<<gg, bb>>>(At, WOw, WOb, out);
}

// round 5
// speedup vs baseline: 1.9615x; 1.9615x over previous
#include <cuda_runtime.h>
#include <cuda_bf16.h>
#include <math.h>
#include <stdint.h>

// Problem constants
#define B_  8
#define S_  128
#define N_  64
#define DK_ 256
#define H_  8
#define DH_ 32

static const int M_TOK = B_ * S_ * N_;  // 65536 token rows

// Scratch (device globals — no allocation allowed)
__device__ float g_Qp[(size_t)B_ * S_ * N_ * DK_];
__device__ float g_Kp[(size_t)B_ * S_ * N_ * DK_];
__device__ float g_Vp[(size_t)B_ * S_ * N_ * DK_];
__device__ float g_At[(size_t)B_ * S_ * N_ * DK_];
// Weights converted to bf16 hi/lo, [n][k] layout (n-major), 4 matrices
__device__ __nv_bfloat16 g_Whi[4 * 256 * 256];
__device__ __nv_bfloat16 g_Wlo[4 * 256 * 256];

// ---------------------------------------------------------------------------
// Weight prep: fp32 W[k][n] (256x256) -> bf16 hi/lo in [n][k] layout.
// ---------------------------------------------------------------------------
struct WPtrs { const float* w[4]; };

__global__ __launch_bounds__(256) void prep_w(
    WPtrs p, __nv_bfloat16* __restrict__ hi, __nv_bfloat16* __restrict__ lo)
{
    __shared__ float t[32][33];
    const float* W = p.w[blockIdx.z];
    __nv_bfloat16* Hp = hi + (size_t)blockIdx.z * 65536;
    __nv_bfloat16* Lp = lo + (size_t)blockIdx.z * 65536;
    int k0 = blockIdx.x * 32, n0 = blockIdx.y * 32;
    int tx = threadIdx.x;          // 0..31
    int ty = threadIdx.y;          // 0..7
    #pragma unroll
    for (int j = 0; j < 4; j++)
        t[ty + 8 * j][tx] = W[(size_t)(k0 + ty + 8 * j) * 256 + n0 + tx];
    __syncthreads();
    #pragma unroll
    for (int j = 0; j < 4; j++) {
        int n = ty + 8 * j;
        float x = t[tx][n];
        __nv_bfloat16 h = __float2bfloat16(x);
        Hp[(size_t)(n0 + n) * 256 + k0 + tx] = h;
        Lp[(size_t)(n0 + n) * 256 + k0 + tx] =
            __float2bfloat16(x - __bfloat162float(h));
    }
}

// ---------------------------------------------------------------------------
// bf16 split-precision tensor-core GEMM:
// C[M,256] = A[M,256] @ W[256,256] + bias, via 3-pass (hi*hi + hi*lo + lo*hi)
// BM=128, BN=64, BK=32. 256 threads (8 warps, 4x2 layout, warp tile 32x32).
// ---------------------------------------------------------------------------
__device__ __forceinline__ void mma_bf16(float* c, const uint32_t* a,
                                         const uint32_t* b)
{
    asm volatile(
        "mma.sync.aligned.m16n8k16.row.col.f32.bf16.bf16.f32 "
        "{%0,%1,%2,%3}, {%4,%5,%6,%7}, {%8,%9}, {%0,%1,%2,%3};\n"
        : "+f"(c[0]), "+f"(c[1]), "+f"(c[2]), "+f"(c[3])
        : "r"(a[0]), "r"(a[1]), "r"(a[2]), "r"(a[3]), "r"(b[0]), "r"(b[1]));
}

__global__ __launch_bounds__(256) void gemm_mma(
    const float* __restrict__ A, const __nv_bfloat16* __restrict__ Whi,
    const __nv_bfloat16* __restrict__ Wlo, const float* __restrict__ bias,
    float* __restrict__ C)
{
    __shared__ __nv_bfloat16 Ah[128][40];
    __shared__ __nv_bfloat16 Al[128][40];
    __shared__ __nv_bfloat16 Bh[64][40];
    __shared__ __nv_bfloat16 Bl[64][40];

    const int tid = threadIdx.x;
    const int warp = tid >> 5, lane = tid & 31;
    const int wm = warp >> 1;       // 0..3 -> m offset 32*wm
    const int wn = warp & 1;        // 0..1 -> n offset 32*wn
    const int rowBase = blockIdx.x * 128;
    const int colBase = blockIdx.y * 64;
    const int gid = lane >> 2, tig = lane & 3;

    float acc[2][4][4];
    #pragma unroll
    for (int i = 0; i < 2; i++)
        #pragma unroll
        for (int j = 0; j < 4; j++)
            #pragma unroll
            for (int q = 0; q < 4; q++) acc[i][j][q] = 0.0f;

    for (int kk = 0; kk < 256; kk += 32) {
        // --- A tile: 128 rows x 32 k, fp32 -> bf16 hi/lo
        #pragma unroll
        for (int i = 0; i < 4; i++) {
            int id = tid + i * 256;
            int r = id >> 3, v = id & 7;
            float4 a = *reinterpret_cast<const float4*>(
                &A[(size_t)(rowBase + r) * 256 + kk + v * 4]);
            float xs[4] = {a.x, a.y, a.z, a.w};
            __nv_bfloat16 h[4], l[4];
            #pragma unroll
            for (int q = 0; q < 4; q++) {
                h[q] = __float2bfloat16(xs[q]);
                l[q] = __float2bfloat16(xs[q] - __bfloat162float(h[q]));
            }
            *reinterpret_cast<__nv_bfloat162*>(&Ah[r][v * 4])     = {h[0], h[1]};
            *reinterpret_cast<__nv_bfloat162*>(&Ah[r][v * 4 + 2]) = {h[2], h[3]};
            *reinterpret_cast<__nv_bfloat162*>(&Al[r][v * 4])     = {l[0], l[1]};
            *reinterpret_cast<__nv_bfloat162*>(&Al[r][v * 4 + 2]) = {l[2], l[3]};
        }
        // --- B tile: 64 n-rows x 32 k bf16, already [n][k]
        {
            int r = tid >> 2;   // n row 0..63
            int v = tid & 3;    // 8-bf16 chunk
            *reinterpret_cast<uint4*>(&Bh[r][v * 8]) =
                *reinterpret_cast<const uint4*>(
                    &Whi[(size_t)(colBase + r) * 256 + kk + v * 8]);
            *reinterpret_cast<uint4*>(&Bl[r][v * 8]) =
                *reinterpret_cast<const uint4*>(
                    &Wlo[(size_t)(colBase + r) * 256 + kk + v * 8]);
        }
        __syncthreads();

        #pragma unroll
        for (int kt = 0; kt < 2; kt++) {
            const int k0 = kt * 16;
            uint32_t af[2][2][4];
            #pragma unroll
            for (int mt = 0; mt < 2; mt++) {
                int m = wm * 32 + mt * 16;
                af[mt][0][0] = *reinterpret_cast<uint32_t*>(&Ah[m + gid][k0 + tig * 2]);
                af[mt][0][1] = *reinterpret_cast<uint32_t*>(&Ah[m + gid + 8][k0 + tig * 2]);
                af[mt][0][2] = *reinterpret_cast<uint32_t*>(&Ah[m + gid][k0 + tig * 2 + 8]);
                af[mt][0][3] = *reinterpret_cast<uint32_t*>(&Ah[m + gid + 8][k0 + tig * 2 + 8]);
                af[mt][1][0] = *reinterpret_cast<uint32_t*>(&Al[m + gid][k0 + tig * 2]);
                af[mt][1][1] = *reinterpret_cast<uint32_t*>(&Al[m + gid + 8][k0 + tig * 2]);
                af[mt][1][2] = *reinterpret_cast<uint32_t*>(&Al[m + gid][k0 + tig * 2 + 8]);
                af[mt][1][3] = *reinterpret_cast<uint32_t*>(&Al[m + gid + 8][k0 + tig * 2 + 8]);
            }
            uint32_t bfr[4][2][2];
            #pragma unroll
            for (int nt = 0; nt < 4; nt++) {
                int n = wn * 32 + nt * 8;
                bfr[nt][0][0] = *reinterpret_cast<uint32_t*>(&Bh[n + gid][k0 + tig * 2]);
                bfr[nt][0][1] = *reinterpret_cast<uint32_t*>(&Bh[n + gid][k0 + tig * 2 + 8]);
                bfr[nt][1][0] = *reinterpret_cast<uint32_t*>(&Bl[n + gid][k0 + tig * 2]);
                bfr[nt][1][1] = *reinterpret_cast<uint32_t*>(&Bl[n + gid][k0 + tig * 2 + 8]);
            }
            #pragma unroll
            for (int mt = 0; mt < 2; mt++)
                #pragma unroll
                for (int nt = 0; nt < 4; nt++) {
                    mma_bf16(acc[mt][nt], af[mt][0], bfr[nt][0]);  // hi*hi
                    mma_bf16(acc[mt][nt], af[mt][0], bfr[nt][1]);  // hi*lo
                    mma_bf16(acc[mt][nt], af[mt][1], bfr[nt][0]);  // lo*hi
                }
        }
        __syncthreads();
    }

    // Epilogue
    #pragma unroll
    for (int mt = 0; mt < 2; mt++) {
        #pragma unroll
        for (int nt = 0; nt < 4; nt++) {
            int m = rowBase + wm * 32 + mt * 16;
            int n = colBase + wn * 32 + nt * 8 + tig * 2;
            float2 bv = *reinterpret_cast<const float2*>(&bias[n]);
            float2 o0 = {acc[mt][nt][0] + bv.x, acc[mt][nt][1] + bv.y};
            float2 o1 = {acc[mt][nt][2] + bv.x, acc[mt][nt][3] + bv.y};
            *reinterpret_cast<float2*>(&C[(size_t)(m + gid) * 256 + n]) = o0;
            *reinterpret_cast<float2*>(&C[(size_t)(m + gid + 8) * 256 + n]) = o1;
        }
    }
}

// ---------------------------------------------------------------------------
// Attention: one block per (b, s, h). N=64 agents, DH=32. Register-tiled.
// ---------------------------------------------------------------------------
__global__ __launch_bounds__(256) void attn_kernel(float* __restrict__ w_out)
{
    __shared__ float Qt[32][68];   // [d][n]
    __shared__ float Kt[32][68];   // [d][m]
    __shared__ float Vs[64][36];   // [m][d]
    __shared__ float P[64][68];    // [n][m]

    const int blk = blockIdx.x;            // ((b*S + s) * H + h)
    const int h = blk % H_;
    const int bs = blk / H_;
    const int s = bs % S_;
    const int b = bs / S_;

    const size_t base = ((size_t)(b * S_ + s) * N_) * DK_ + (size_t)h * DH_;
    const int tid = threadIdx.x;

    // ---- Load Q/K (transposed) and V (direct)
    #pragma unroll
    for (int i = 0; i < 2; i++) {
        int id = tid + i * 256;
        int n = id >> 3, v = id & 7;
        size_t g = base + (size_t)n * DK_ + v * 4;
        float4 q = *reinterpret_cast<const float4*>(&g_Qp[g]);
        Qt[v * 4 + 0][n] = q.x; Qt[v * 4 + 1][n] = q.y;
        Qt[v * 4 + 2][n] = q.z; Qt[v * 4 + 3][n] = q.w;
        float4 k = *reinterpret_cast<const float4*>(&g_Kp[g]);
        Kt[v * 4 + 0][n] = k.x; Kt[v * 4 + 1][n] = k.y;
        Kt[v * 4 + 2][n] = k.z; Kt[v * 4 + 3][n] = k.w;
        float4 vv = *reinterpret_cast<const float4*>(&g_Vp[g]);
        *reinterpret_cast<float4*>(&Vs[n][v * 4]) = vv;
    }
    __syncthreads();

    // ---- Scores: 4x4 register tile per thread
    {
        const int tx = tid & 15;   // m0 = 4*tx
        const int ty = tid >> 4;   // n0 = 4*ty
        float acc[4][4] = {};
        #pragma unroll
        for (int d = 0; d < 32; d++) {
            float4 qv = *reinterpret_cast<const float4*>(&Qt[d][ty * 4]);
            float4 kv = *reinterpret_cast<const float4*>(&Kt[d][tx * 4]);
            float qa[4] = {qv.x, qv.y, qv.z, qv.w};
            float ka[4] = {kv.x, kv.y, kv.z, kv.w};
            #pragma unroll
            for (int i = 0; i < 4; i++)
                #pragma unroll
                for (int j = 0; j < 4; j++)
                    acc[i][j] += qa[i] * ka[j];
        }
        const float scale = 0.17677669529663687f;  // 1/sqrt(32)
        #pragma unroll
        for (int i = 0; i < 4; i++) {
            float4 o = {acc[i][0] * scale, acc[i][1] * scale,
                        acc[i][2] * scale, acc[i][3] * scale};
            *reinterpret_cast<float4*>(&P[ty * 4 + i][tx * 4]) = o;
        }
    }
    __syncthreads();

    // ---- Softmax: 4 threads per row, 16 cols each, shuffle reduce
    const size_t wbase = ((size_t)((b * H_ + h) * S_ + s)) * (size_t)(N_ * N_);
    {
        const int r = tid >> 2;
        const int qq = tid & 3;
        float x[16];
        #pragma unroll
        for (int j = 0; j < 4; j++) {
            float4 v = *reinterpret_cast<const float4*>(&P[r][qq * 16 + j * 4]);
            x[j * 4 + 0] = v.x; x[j * 4 + 1] = v.y;
            x[j * 4 + 2] = v.z; x[j * 4 + 3] = v.w;
        }
        float mx = -INFINITY;
        #pragma unroll
        for (int j = 0; j < 16; j++) mx = fmaxf(mx, x[j]);
        mx = fmaxf(mx, __shfl_xor_sync(0xffffffffu, mx, 1));
        mx = fmaxf(mx, __shfl_xor_sync(0xffffffffu, mx, 2));
        float sum = 0.0f;
        #pragma unroll
        for (int j = 0; j < 16; j++) {
            x[j] = __expf(x[j] - mx);
            sum += x[j];
        }
        sum += __shfl_xor_sync(0xffffffffu, sum, 1);
        sum += __shfl_xor_sync(0xffffffffu, sum, 2);
        float rinv = 1.0f / sum;
        #pragma unroll
        for (int j = 0; j < 4; j++) {
            float4 o = {x[j * 4 + 0] * rinv, x[j * 4 + 1] * rinv,
                        x[j * 4 + 2] * rinv, x[j * 4 + 3] * rinv};
            *reinterpret_cast<float4*>(&P[r][qq * 16 + j * 4]) = o;
            *reinterpret_cast<float4*>(&w_out[wbase + (size_t)r * 64 + qq * 16 + j * 4]) = o;
        }
    }
    __syncthreads();

    // ---- attn = P @ V : 2n x 4d register tile per thread
    {
        const int dx = tid & 7;    // d0 = 4*dx
        const int ny = tid >> 3;   // n0 = 2*ny
        float a0[4] = {}, a1[4] = {};
        #pragma unroll 4
        for (int m = 0; m < 64; m++) {
            float4 vv = *reinterpret_cast<const float4*>(&Vs[m][dx * 4]);
            float p0 = P[ny * 2][m];
            float p1 = P[ny * 2 + 1][m];
            a0[0] += p0 * vv.x; a0[1] += p0 * vv.y;
            a0[2] += p0 * vv.z; a0[3] += p0 * vv.w;
            a1[0] += p1 * vv.x; a1[1] += p1 * vv.y;
            a1[2] += p1 * vv.z; a1[3] += p1 * vv.w;
        }
        size_t g0 = base + (size_t)(ny * 2) * DK_ + dx * 4;
        *reinterpret_cast<float4*>(&g_At[g0])       = {a0[0], a0[1], a0[2], a0[3]};
        *reinterpret_cast<float4*>(&g_At[g0 + DK_]) = {a1[0], a1[1], a1[2], a1[3]};
    }
}

// ---------------------------------------------------------------------------
extern "C" void kernel_launch(void* const* d_in, const int* in_sizes, int n_in,
                              void* d_out, int out_size)
{
    const float* q   = (const float*)d_in[0];
    const float* k   = (const float*)d_in[1];
    const float* v   = (const float*)d_in[2];
    const float* WQw = (const float*)d_in[3];
    const float* WQb = (const float*)d_in[4];
    const float* WKw = (const float*)d_in[5];
    const float* WKb = (const float*)d_in[6];
    const float* WVw = (const float*)d_in[7];
    const float* WVb = (const float*)d_in[8];
    const float* WOw = (const float*)d_in[9];
    const float* WOb = (const float*)d_in[10];

    float* out = (float*)d_out;                              // (B,S,N,DK)
    float* wts = out + (size_t)M_TOK * DK_;                  // (B,H,S,N,N)

    float *Qp, *Kp, *Vp, *At;
    __nv_bfloat16 *Whi, *Wlo;
    cudaGetSymbolAddress((void**)&Qp, g_Qp);
    cudaGetSymbolAddress((void**)&Kp, g_Kp);
    cudaGetSymbolAddress((void**)&Vp, g_Vp);
    cudaGetSymbolAddress((void**)&At, g_At);
    cudaGetSymbolAddress((void**)&Whi, g_Whi);
    cudaGetSymbolAddress((void**)&Wlo, g_Wlo);

    // Weight conversion (fp32 -> bf16 hi/lo, transposed to [n][k])
    WPtrs wp;
    wp.w[0] = WQw; wp.w[1] = WKw; wp.w[2] = WVw; wp.w[3] = WOw;
    prep_w<<<dim3(8, 8, 4), dim3(32, 8)>>>(wp, Whi, Wlo);

    dim3 gg(M_TOK / 128, 256 / 64);   // (512, 4)
    dim3 bb(256);

    gemm_mma<<<gg, bb>>>(q, Whi + 0 * 65536, Wlo + 0 * 65536, WQb, Qp);
    gemm_mma<<<gg, bb>>>(k, Whi + 1 * 65536, Wlo + 1 * 65536, WKb, Kp);
    gemm_mma<<<gg, bb>>>(v, Whi + 2 * 65536, Wlo + 2 * 65536, WVb, Vp);

    attn_kernel<<<B_ * S_ * H_, 256>>>(wts);

    gemm_mma<<<gg, bb>>>(At, Whi + 3 * 65536, Wlo + 3 * 65536, WOb, out);
}